// round 5
// baseline (speedup 1.0000x reference)
#include <cuda_runtime.h>
#include <cuda_bf16.h>
#include <cstdint>
#include <cstddef>

#define B_DIM    4096
#define IN_DIM   3136
#define FEAT_DIM 6272
#define OUT_DIM  500

// ---------------- static device scratch (allocation-free) ----------------
__device__ __nv_bfloat16 g_xb [(size_t)B_DIM * IN_DIM];     // x as bf16 (exact)
__device__ __nv_bfloat16 g_s1b[(size_t)B_DIM * FEAT_DIM];   // hidden spikes bf16 (exact)
__device__ __nv_bfloat16 g_w1l[3ull * FEAT_DIM * IN_DIM];   // W1 limbs hi/mid/lo
__device__ __nv_bfloat16 g_w2l[3ull * OUT_DIM * FEAT_DIM];  // W2 limbs

// ---------------- PTX helpers (baseline sm_80+ features only) ----------------
__device__ __forceinline__ uint32_t smem_u32(const void* p) {
    uint32_t a;
    asm("{ .reg .u64 t; cvta.to.shared.u64 t, %1; cvt.u32.u64 %0, t; }" : "=r"(a) : "l"(p));
    return a;
}
__device__ __forceinline__ void cp_async16(uint32_t dst, const void* src, int src_bytes) {
    asm volatile("cp.async.cg.shared.global [%0], [%1], 16, %2;"
                 :: "r"(dst), "l"(src), "r"(src_bytes) : "memory");
}
__device__ __forceinline__ void cp_commit() {
    asm volatile("cp.async.commit_group;" ::: "memory");
}
template <int N>
__device__ __forceinline__ void cp_wait() {
    asm volatile("cp.async.wait_group %0;" :: "n"(N) : "memory");
}
__device__ __forceinline__ void ldm_x4(uint32_t* r, uint32_t a) {
    asm volatile("ldmatrix.sync.aligned.m8n8.x4.shared.b16 {%0,%1,%2,%3}, [%4];"
                 : "=r"(r[0]), "=r"(r[1]), "=r"(r[2]), "=r"(r[3]) : "r"(a));
}
__device__ __forceinline__ void mma_bf16(float* c, const uint32_t* a, uint32_t b0, uint32_t b1) {
    asm volatile(
        "mma.sync.aligned.m16n8k16.row.col.f32.bf16.bf16.f32 "
        "{%0,%1,%2,%3}, {%4,%5,%6,%7}, {%8,%9}, {%0,%1,%2,%3};"
        : "+f"(c[0]), "+f"(c[1]), "+f"(c[2]), "+f"(c[3])
        : "r"(a[0]), "r"(a[1]), "r"(a[2]), "r"(a[3]), "r"(b0), "r"(b1));
}

// ---------------- converter kernels ----------------
__global__ void conv_bf16_kernel(const float4* __restrict__ in,
                                 __nv_bfloat162* __restrict__ out, int n4) {
    int i = blockIdx.x * blockDim.x + threadIdx.x;
    if (i < n4) {
        float4 v = in[i];
        out[i * 2 + 0] = __nv_bfloat162(__float2bfloat16_rn(v.x), __float2bfloat16_rn(v.y));
        out[i * 2 + 1] = __nv_bfloat162(__float2bfloat16_rn(v.z), __float2bfloat16_rn(v.w));
    }
}

// exact 3-limb split: w == hi + mid + lo (each residual exact in fp32)
__global__ void split3_kernel(const float4* __restrict__ in,
                              __nv_bfloat16* __restrict__ limbs, size_t n, int n4) {
    int i = blockIdx.x * blockDim.x + threadIdx.x;
    if (i >= n4) return;
    float4 v = in[i];
    float w[4] = {v.x, v.y, v.z, v.w};
    __nv_bfloat16 hi[4], mi[4], lo[4];
#pragma unroll
    for (int j = 0; j < 4; j++) {
        float f = w[j];
        hi[j] = __float2bfloat16_rn(f);
        float r1 = f - __bfloat162float(hi[j]);
        mi[j] = __float2bfloat16_rn(r1);
        float r2 = r1 - __bfloat162float(mi[j]);
        lo[j] = __float2bfloat16_rn(r2);
    }
    __nv_bfloat162* o0 = reinterpret_cast<__nv_bfloat162*>(limbs);
    __nv_bfloat162* o1 = reinterpret_cast<__nv_bfloat162*>(limbs + n);
    __nv_bfloat162* o2 = reinterpret_cast<__nv_bfloat162*>(limbs + 2 * n);
    o0[i * 2 + 0] = __nv_bfloat162(hi[0], hi[1]); o0[i * 2 + 1] = __nv_bfloat162(hi[2], hi[3]);
    o1[i * 2 + 0] = __nv_bfloat162(mi[0], mi[1]); o1[i * 2 + 1] = __nv_bfloat162(mi[2], mi[3]);
    o2[i * 2 + 0] = __nv_bfloat162(lo[0], lo[1]); o2[i * 2 + 1] = __nv_bfloat162(lo[2], lo[3]);
}

// ---------------- fused mma.sync spike GEMM ----------------
//  C[M,Nout] = step( A[M,K] @ W[Nout,K]^T ),  W given as 3 bf16 limbs
//  (folded into the k-loop, accumulating into the same fp32 accumulators).
//  256 threads = 8 warps laid out 4(m) x 2(n); warp tile = WM x 64.
//  CTA tile = (4*WM) x 128, BK = 32.  Smem rows are 64B, xor-swizzled.
#define STAGES 3

template <int WM, bool OUT_BF16>
__global__ __launch_bounds__(256)
void spike_mma_gemm(const __nv_bfloat16* __restrict__ A,
                    const __nv_bfloat16* __restrict__ Wl, size_t limbStride,
                    void* __restrict__ Cout, int K, int Nout)
{
    constexpr int CTA_M = 4 * WM;
    constexpr int A_BYTES = CTA_M * 64;              // A tile per stage
    constexpr int STAGE_BYTES = A_BYTES + 3 * 128 * 64;
    constexpr int MT = WM / 16;                      // m16 tiles per warp

    extern __shared__ char smem[];
    const int tid  = threadIdx.x;
    const int lane = tid & 31;
    const int wid  = tid >> 5;
    const int wm   = wid & 3;       // warp row
    const int wn   = wid >> 2;      // warp col (64 cols each)
    const int rowBase = blockIdx.x * CTA_M;  // M-fast grid: W slab reused in L2
    const int colBase = blockIdx.y * 128;

    const int rL  = lane & 15;
    const int ccL = lane >> 4;

    float acc[MT][8][4];
#pragma unroll
    for (int i = 0; i < MT; i++)
#pragma unroll
        for (int j = 0; j < 8; j++)
#pragma unroll
            for (int k = 0; k < 4; k++) acc[i][j][k] = 0.0f;

    const uint32_t smem_base = smem_u32(smem);
    const int ITERS = K / 32;

    // ---- async stage loader: A (CTA_M*4 16B chunks) + 3 B limb tiles ----
    auto load_stage = [&](int it) {
        const int s  = it % STAGES;
        const int kt = it * 32;
        const uint32_t stA = smem_base + s * STAGE_BYTES;
        const uint32_t stB = stA + A_BYTES;
#pragma unroll
        for (int i = 0; i < CTA_M / 64; i++) {
            const int idx = tid + i * 256;          // 0..CTA_M*4-1
            const int r = idx >> 2, c = idx & 3;
            const uint32_t d = stA + r * 64 + (((c ^ (r & 3)) << 4));
            cp_async16(d, A + (size_t)(rowBase + r) * K + kt + c * 8, 16);
        }
#pragma unroll
        for (int j = 0; j < 6; j++) {
            const int idx = tid + j * 256;          // 0..1535
            const int limb = idx >> 9, rem = idx & 511;
            const int r = rem >> 2, c = rem & 3;
            const int gn = colBase + r;
            const int ok = (gn < Nout);
            const int gns = ok ? gn : (Nout - 1);   // safe address, zero-fill when !ok
            const uint32_t d = stB + limb * 8192 + r * 64 + (((c ^ (r & 3)) << 4));
            cp_async16(d, Wl + (size_t)limb * limbStride + (size_t)gns * K + kt + c * 8,
                       ok ? 16 : 0);
        }
        cp_commit();
    };

    load_stage(0);
    if (ITERS > 1) load_stage(1);

    for (int it = 0; it < ITERS; ++it) {
        cp_wait<1>();
        __syncthreads();
        if (it + 2 < ITERS) load_stage(it + 2);

        const int s = it % STAGES;
        const uint32_t stA = smem_base + s * STAGE_BYTES;
        const uint32_t stB = stA + A_BYTES;

#pragma unroll
        for (int ks = 0; ks < 2; ks++) {
            uint32_t afr[MT][4];
#pragma unroll
            for (int mt = 0; mt < MT; mt++) {
                const int row = wm * WM + mt * 16 + rL;
                const uint32_t ad = stA + row * 64 + (((ccL + 2 * ks) ^ (row & 3)) << 4);
                ldm_x4(afr[mt], ad);
            }
#pragma unroll
            for (int limb = 0; limb < 3; limb++) {
                uint32_t bfr[4][4];
#pragma unroll
                for (int nb = 0; nb < 4; nb++) {
                    const int row = wn * 64 + nb * 16 + rL;
                    const uint32_t bd = stB + limb * 8192 + row * 64 +
                                        (((ccL + 2 * ks) ^ (row & 3)) << 4);
                    ldm_x4(bfr[nb], bd);
                }
#pragma unroll
                for (int mt = 0; mt < MT; mt++)
#pragma unroll
                    for (int nb = 0; nb < 4; nb++) {
                        mma_bf16(acc[mt][nb * 2 + 0], afr[mt], bfr[nb][0], bfr[nb][2]);
                        mma_bf16(acc[mt][nb * 2 + 1], afr[mt], bfr[nb][1], bfr[nb][3]);
                    }
            }
        }
    }

    // ---- epilogue: threshold + direct stores (spikes are exact in bf16) ----
    const int g = lane >> 2;
    const int t = lane & 3;
#pragma unroll
    for (int mt = 0; mt < MT; mt++) {
#pragma unroll
        for (int nt = 0; nt < 8; nt++) {
            const float* c = acc[mt][nt];
            const int row = rowBase + wm * WM + mt * 16 + g;
            const int col = colBase + wn * 64 + nt * 8 + 2 * t;
            if (OUT_BF16) {
                __nv_bfloat16* o = (__nv_bfloat16*)Cout;
                __nv_bfloat162 v0(__float2bfloat16(c[0] >= 1.0f ? 1.0f : 0.0f),
                                  __float2bfloat16(c[1] >= 1.0f ? 1.0f : 0.0f));
                __nv_bfloat162 v1(__float2bfloat16(c[2] >= 1.0f ? 1.0f : 0.0f),
                                  __float2bfloat16(c[3] >= 1.0f ? 1.0f : 0.0f));
                *reinterpret_cast<__nv_bfloat162*>(o + (size_t)row * Nout + col) = v0;
                *reinterpret_cast<__nv_bfloat162*>(o + (size_t)(row + 8) * Nout + col) = v1;
            } else {
                float* o = (float*)Cout;
                if (col < Nout) {   // Nout even, col even -> pair fits
                    float2 v0 = make_float2(c[0] >= 1.0f ? 1.0f : 0.0f,
                                            c[1] >= 1.0f ? 1.0f : 0.0f);
                    float2 v1 = make_float2(c[2] >= 1.0f ? 1.0f : 0.0f,
                                            c[3] >= 1.0f ? 1.0f : 0.0f);
                    *reinterpret_cast<float2*>(o + (size_t)row * Nout + col) = v0;
                    *reinterpret_cast<float2*>(o + (size_t)(row + 8) * Nout + col) = v1;
                }
            }
        }
    }
}

// ---------------- host launcher ----------------
extern "C" void kernel_launch(void* const* d_in, const int* in_sizes, int n_in,
                              void* d_out, int out_size)
{
    const float* x  = (const float*)d_in[0];  // [4096, 3136] binary
    const float* W1 = (const float*)d_in[1];  // [6272, 3136]
    const float* W2 = (const float*)d_in[2];  // [500, 6272]
    float* out = (float*)d_out;               // [4096, 500]

    __nv_bfloat16 *xb, *s1b, *w1l, *w2l;
    cudaGetSymbolAddress((void**)&xb,  g_xb);
    cudaGetSymbolAddress((void**)&s1b, g_s1b);
    cudaGetSymbolAddress((void**)&w1l, g_w1l);
    cudaGetSymbolAddress((void**)&w2l, g_w2l);

    // converters
    {
        int n4 = (B_DIM * IN_DIM) / 4;
        conv_bf16_kernel<<<(n4 + 255) / 256, 256>>>(
            (const float4*)x, (__nv_bfloat162*)xb, n4);
    }
    {
        size_t n = (size_t)FEAT_DIM * IN_DIM;
        int n4 = (int)(n / 4);
        split3_kernel<<<(n4 + 255) / 256, 256>>>((const float4*)W1, w1l, n, n4);
    }
    {
        size_t n = (size_t)OUT_DIM * FEAT_DIM;
        int n4 = (int)(n / 4);
        split3_kernel<<<(n4 + 255) / 256, 256>>>((const float4*)W2, w2l, n, n4);
    }

    // GEMM1: s1 = step(x @ W1^T)  [4096 x 6272], CTA tile 256x128, warp 64x64
    {
        constexpr int SMEM = STAGES * (256 * 64 + 3 * 128 * 64);   // 120 KB
        cudaFuncSetAttribute(spike_mma_gemm<64, true>,
                             cudaFuncAttributeMaxDynamicSharedMemorySize, SMEM);
        dim3 grid(B_DIM / 256, FEAT_DIM / 128);          // (16, 49) M-fast
        spike_mma_gemm<64, true><<<grid, 256, SMEM>>>(
            xb, w1l, (size_t)FEAT_DIM * IN_DIM, (void*)s1b, IN_DIM, FEAT_DIM);
    }
    // GEMM2: out = step(s1 @ W2^T)  [4096 x 500], CTA tile 128x128, warp 32x64
    {
        constexpr int SMEM = STAGES * (128 * 64 + 3 * 128 * 64);   // 96 KB
        cudaFuncSetAttribute(spike_mma_gemm<32, false>,
                             cudaFuncAttributeMaxDynamicSharedMemorySize, SMEM);
        dim3 grid(B_DIM / 128, (OUT_DIM + 127) / 128);   // (32, 4)
        spike_mma_gemm<32, false><<<grid, 256, SMEM>>>(
            s1b, w2l, (size_t)OUT_DIM * FEAT_DIM, (void*)out, FEAT_DIM, OUT_DIM);
    }
}

// round 8
// speedup vs baseline: 1.3089x; 1.3089x over previous
#include <cuda_runtime.h>
#include <cuda_bf16.h>
#include <cstdint>
#include <cstddef>

#define B_DIM    4096
#define IN_DIM   3136
#define FEAT_DIM 6272
#define OUT_DIM  500
#define WL_CAP   (1 << 20)

// ---------------- static device scratch (allocation-free) ----------------
__device__ __nv_bfloat16 g_xb [(size_t)B_DIM * IN_DIM];     // x as bf16 (exact)
__device__ __nv_bfloat16 g_s1b[(size_t)B_DIM * FEAT_DIM];   // hidden spikes bf16 (exact)
__device__ __nv_bfloat16 g_w1l[2ull * FEAT_DIM * IN_DIM];   // W1 limbs hi/mid
__device__ __nv_bfloat16 g_w2l[3ull * OUT_DIM * FEAT_DIM];  // W2 limbs hi/mid/lo
__device__ float         g_cb1[FEAT_DIM];                   // per-col residual bound
__device__ int           g_cnt;                             // worklist counter
__device__ unsigned      g_list[WL_CAP];                    // ambiguous v1 elements

// ---------------- PTX helpers ----------------
__device__ __forceinline__ uint32_t smem_u32(const void* p) {
    uint32_t a;
    asm("{ .reg .u64 t; cvta.to.shared.u64 t, %1; cvt.u32.u64 %0, t; }" : "=r"(a) : "l"(p));
    return a;
}
__device__ __forceinline__ void cp_async16(uint32_t dst, const void* src, int src_bytes) {
    asm volatile("cp.async.cg.shared.global [%0], [%1], 16, %2;"
                 :: "r"(dst), "l"(src), "r"(src_bytes) : "memory");
}
__device__ __forceinline__ void cp_commit() {
    asm volatile("cp.async.commit_group;" ::: "memory");
}
template <int N>
__device__ __forceinline__ void cp_wait() {
    asm volatile("cp.async.wait_group %0;" :: "n"(N) : "memory");
}
__device__ __forceinline__ void ldm_x4(uint32_t* r, uint32_t a) {
    asm volatile("ldmatrix.sync.aligned.m8n8.x4.shared.b16 {%0,%1,%2,%3}, [%4];"
                 : "=r"(r[0]), "=r"(r[1]), "=r"(r[2]), "=r"(r[3]) : "r"(a));
}
__device__ __forceinline__ void mma_bf16(float* c, const uint32_t* a, uint32_t b0, uint32_t b1) {
    asm volatile(
        "mma.sync.aligned.m16n8k16.row.col.f32.bf16.bf16.f32 "
        "{%0,%1,%2,%3}, {%4,%5,%6,%7}, {%8,%9}, {%0,%1,%2,%3};"
        : "+f"(c[0]), "+f"(c[1]), "+f"(c[2]), "+f"(c[3])
        : "r"(a[0]), "r"(a[1]), "r"(a[2]), "r"(a[3]), "r"(b0), "r"(b1));
}

// ---------------- converter kernels ----------------
__global__ void conv_bf16_kernel(const float4* __restrict__ in,
                                 __nv_bfloat162* __restrict__ out, int n4) {
    int i = blockIdx.x * blockDim.x + threadIdx.x;
    if (i < n4) {
        float4 v = in[i];
        out[i * 2 + 0] = __nv_bfloat162(__float2bfloat16_rn(v.x), __float2bfloat16_rn(v.y));
        out[i * 2 + 1] = __nv_bfloat162(__float2bfloat16_rn(v.z), __float2bfloat16_rn(v.w));
    }
}

// 2-limb split: hi + mid (residual r2 = w-hi-mid handled by bound+fixup)
__global__ void split2_kernel(const float4* __restrict__ in,
                              __nv_bfloat16* __restrict__ limbs, size_t n, int n4) {
    int i = blockIdx.x * blockDim.x + threadIdx.x;
    if (i >= n4) return;
    float4 v = in[i];
    float w[4] = {v.x, v.y, v.z, v.w};
    __nv_bfloat16 hi[4], mi[4];
#pragma unroll
    for (int j = 0; j < 4; j++) {
        float f = w[j];
        hi[j] = __float2bfloat16_rn(f);
        float r1 = f - __bfloat162float(hi[j]);
        mi[j] = __float2bfloat16_rn(r1);
    }
    __nv_bfloat162* o0 = reinterpret_cast<__nv_bfloat162*>(limbs);
    __nv_bfloat162* o1 = reinterpret_cast<__nv_bfloat162*>(limbs + n);
    o0[i * 2 + 0] = __nv_bfloat162(hi[0], hi[1]); o0[i * 2 + 1] = __nv_bfloat162(hi[2], hi[3]);
    o1[i * 2 + 0] = __nv_bfloat162(mi[0], mi[1]); o1[i * 2 + 1] = __nv_bfloat162(mi[2], mi[3]);
}

// exact 3-limb split (GEMM2 weights)
__global__ void split3_kernel(const float4* __restrict__ in,
                              __nv_bfloat16* __restrict__ limbs, size_t n, int n4) {
    int i = blockIdx.x * blockDim.x + threadIdx.x;
    if (i >= n4) return;
    float4 v = in[i];
    float w[4] = {v.x, v.y, v.z, v.w};
    __nv_bfloat16 hi[4], mi[4], lo[4];
#pragma unroll
    for (int j = 0; j < 4; j++) {
        float f = w[j];
        hi[j] = __float2bfloat16_rn(f);
        float r1 = f - __bfloat162float(hi[j]);
        mi[j] = __float2bfloat16_rn(r1);
        float r2 = r1 - __bfloat162float(mi[j]);
        lo[j] = __float2bfloat16_rn(r2);
    }
    __nv_bfloat162* o0 = reinterpret_cast<__nv_bfloat162*>(limbs);
    __nv_bfloat162* o1 = reinterpret_cast<__nv_bfloat162*>(limbs + n);
    __nv_bfloat162* o2 = reinterpret_cast<__nv_bfloat162*>(limbs + 2 * n);
    o0[i * 2 + 0] = __nv_bfloat162(hi[0], hi[1]); o0[i * 2 + 1] = __nv_bfloat162(hi[2], hi[3]);
    o1[i * 2 + 0] = __nv_bfloat162(mi[0], mi[1]); o1[i * 2 + 1] = __nv_bfloat162(mi[2], mi[3]);
    o2[i * 2 + 0] = __nv_bfloat162(lo[0], lo[1]); o2[i * 2 + 1] = __nv_bfloat162(lo[2], lo[3]);
}

// per-column residual bound: cb[j] = 1.0001 * sum_i |W[j,i] - hi - mid| + slack
__global__ void colbound_kernel(const float* __restrict__ W, float* __restrict__ cb, int K) {
    const int j = blockIdx.x * (blockDim.x >> 5) + (threadIdx.x >> 5);
    const int lane = threadIdx.x & 31;
    const float* wr = W + (size_t)j * K;
    float s = 0.0f;
    for (int i = lane; i < K; i += 32) {
        float f = wr[i];
        __nv_bfloat16 h = __float2bfloat16_rn(f);
        float r1 = f - __bfloat162float(h);
        __nv_bfloat16 m = __float2bfloat16_rn(r1);
        s += fabsf(r1 - __bfloat162float(m));
    }
#pragma unroll
    for (int o = 16; o; o >>= 1) s += __shfl_xor_sync(0xFFFFFFFFu, s, o);
    if (lane == 0) cb[j] = s * 1.0001f + 1e-7f;
}

// exact fp32 recompute of ambiguous v1 elements -> rewrite s1 spike
__global__ void fixup1_kernel(const float* __restrict__ x, const float* __restrict__ W1,
                              __nv_bfloat16* __restrict__ s1b) {
    const int warp = (blockIdx.x * blockDim.x + threadIdx.x) >> 5;
    const int lane = threadIdx.x & 31;
    const int nwarp = (gridDim.x * blockDim.x) >> 5;
    int cnt = g_cnt; if (cnt > WL_CAP) cnt = WL_CAP;
    for (int w = warp; w < cnt; w += nwarp) {
        const unsigned idx = g_list[w];
        const int b = idx / FEAT_DIM, j = idx % FEAT_DIM;
        const float* xr = x  + (size_t)b * IN_DIM;
        const float* wr = W1 + (size_t)j * IN_DIM;
        float s = 0.0f;
        for (int i = lane; i < IN_DIM; i += 32) s = fmaf(xr[i], wr[i], s);
#pragma unroll
        for (int o = 16; o; o >>= 1) s += __shfl_xor_sync(0xFFFFFFFFu, s, o);
        if (lane == 0)
            s1b[(size_t)b * FEAT_DIM + j] = __float2bfloat16(s >= 1.0f ? 1.0f : 0.0f);
    }
}

// ---------------- fused mma.sync spike GEMM ----------------
//  C[M,Nout] = step( A[M,K] @ W[Nout,K]^T ), W given as NL bf16 limbs.
//  128x128 CTA tile, BK=32, 256 threads = 8 warps (4m x 2n), warp tile 32x64.
//  CHECK: push |v-1| < colbound[col] elements to the fixup worklist.
#define STAGES 3

template <int NL, bool OUT_BF16, bool CHECK>
__global__ __launch_bounds__(256, 2)
void spike_mma_gemm(const __nv_bfloat16* __restrict__ A,
                    const __nv_bfloat16* __restrict__ Wl, size_t limbStride,
                    const float* __restrict__ colbound,
                    void* __restrict__ Cout, int K, int Nout)
{
    constexpr int STAGE_BYTES = (1 + NL) * 128 * 64;

    extern __shared__ char smem[];
    const int tid  = threadIdx.x;
    const int lane = tid & 31;
    const int wid  = tid >> 5;
    const int wm   = wid & 3;
    const int wn   = wid >> 2;
    const int rowBase = blockIdx.x * 128;   // M-fast grid: W slab reused in L2
    const int colBase = blockIdx.y * 128;

    const int rL  = lane & 15;
    const int ccL = lane >> 4;

    float acc[2][8][4];
#pragma unroll
    for (int i = 0; i < 2; i++)
#pragma unroll
        for (int j = 0; j < 8; j++)
#pragma unroll
            for (int k = 0; k < 4; k++) acc[i][j][k] = 0.0f;

    const uint32_t smem_base = smem_u32(smem);
    const int ITERS = K / 32;

    auto load_stage = [&](int it) {
        const int s  = it % STAGES;
        const int kt = it * 32;
        const uint32_t stA = smem_base + s * STAGE_BYTES;
        const uint32_t stB = stA + 128 * 64;
#pragma unroll
        for (int i = 0; i < 2; i++) {
            const int idx = tid * 2 + i;            // 0..511
            const int r = idx >> 2, c = idx & 3;
            const uint32_t d = stA + r * 64 + (((c ^ (r & 3)) << 4));
            cp_async16(d, A + (size_t)(rowBase + r) * K + kt + c * 8, 16);
        }
#pragma unroll
        for (int j = 0; j < 2 * NL; j++) {
            const int idx = tid + j * 256;          // 0..NL*512-1
            const int limb = idx >> 9, rem = idx & 511;
            const int r = rem >> 2, c = rem & 3;
            const int gn = colBase + r;
            const int ok = (gn < Nout);
            const int gns = ok ? gn : (Nout - 1);
            const uint32_t d = stB + limb * 8192 + r * 64 + (((c ^ (r & 3)) << 4));
            cp_async16(d, Wl + (size_t)limb * limbStride + (size_t)gns * K + kt + c * 8,
                       ok ? 16 : 0);
        }
        cp_commit();
    };

    load_stage(0);
    if (ITERS > 1) load_stage(1);

    for (int it = 0; it < ITERS; ++it) {
        cp_wait<1>();
        __syncthreads();
        if (it + 2 < ITERS) load_stage(it + 2);

        const int s = it % STAGES;
        const uint32_t stA = smem_base + s * STAGE_BYTES;
        const uint32_t stB = stA + 128 * 64;

#pragma unroll
        for (int ks = 0; ks < 2; ks++) {
            uint32_t afr[2][4];
#pragma unroll
            for (int mt = 0; mt < 2; mt++) {
                const int row = wm * 32 + mt * 16 + rL;
                const uint32_t ad = stA + row * 64 + (((ccL + 2 * ks) ^ (row & 3)) << 4);
                ldm_x4(afr[mt], ad);
            }
#pragma unroll
            for (int limb = 0; limb < NL; limb++) {
                uint32_t bfr[4][4];
#pragma unroll
                for (int nb = 0; nb < 4; nb++) {
                    const int row = wn * 64 + nb * 16 + rL;
                    const uint32_t bd = stB + limb * 8192 + row * 64 +
                                        (((ccL + 2 * ks) ^ (row & 3)) << 4);
                    ldm_x4(bfr[nb], bd);
                }
#pragma unroll
                for (int mt = 0; mt < 2; mt++)
#pragma unroll
                    for (int nb = 0; nb < 4; nb++) {
                        mma_bf16(acc[mt][nb * 2 + 0], afr[mt], bfr[nb][0], bfr[nb][2]);
                        mma_bf16(acc[mt][nb * 2 + 1], afr[mt], bfr[nb][1], bfr[nb][3]);
                    }
            }
        }
    }

    // ---- epilogue: threshold + stores (+ ambiguity worklist when CHECK) ----
    const int g = lane >> 2;
    const int t = lane & 3;
#pragma unroll
    for (int mt = 0; mt < 2; mt++) {
#pragma unroll
        for (int nt = 0; nt < 8; nt++) {
            const float* c = acc[mt][nt];
            const int row = rowBase + wm * 32 + mt * 16 + g;
            const int col = colBase + wn * 64 + nt * 8 + 2 * t;
            if (CHECK) {
                const float b0 = colbound[col]     + 3e-5f;
                const float b1 = colbound[col + 1] + 3e-5f;
                const float m[4] = {fabsf(c[0] - 1.0f), fabsf(c[1] - 1.0f),
                                    fabsf(c[2] - 1.0f), fabsf(c[3] - 1.0f)};
                const unsigned base0 = (unsigned)row * (unsigned)Nout + col;
                const unsigned base1 = (unsigned)(row + 8) * (unsigned)Nout + col;
                if (m[0] < b0) { int p = atomicAdd(&g_cnt, 1); if (p < WL_CAP) g_list[p] = base0; }
                if (m[1] < b1) { int p = atomicAdd(&g_cnt, 1); if (p < WL_CAP) g_list[p] = base0 + 1; }
                if (m[2] < b0) { int p = atomicAdd(&g_cnt, 1); if (p < WL_CAP) g_list[p] = base1; }
                if (m[3] < b1) { int p = atomicAdd(&g_cnt, 1); if (p < WL_CAP) g_list[p] = base1 + 1; }
            }
            if (OUT_BF16) {
                __nv_bfloat16* o = (__nv_bfloat16*)Cout;
                __nv_bfloat162 v0(__float2bfloat16(c[0] >= 1.0f ? 1.0f : 0.0f),
                                  __float2bfloat16(c[1] >= 1.0f ? 1.0f : 0.0f));
                __nv_bfloat162 v1(__float2bfloat16(c[2] >= 1.0f ? 1.0f : 0.0f),
                                  __float2bfloat16(c[3] >= 1.0f ? 1.0f : 0.0f));
                *reinterpret_cast<__nv_bfloat162*>(o + (size_t)row * Nout + col) = v0;
                *reinterpret_cast<__nv_bfloat162*>(o + (size_t)(row + 8) * Nout + col) = v1;
            } else {
                float* o = (float*)Cout;
                if (col < Nout) {
                    float2 v0 = make_float2(c[0] >= 1.0f ? 1.0f : 0.0f,
                                            c[1] >= 1.0f ? 1.0f : 0.0f);
                    float2 v1 = make_float2(c[2] >= 1.0f ? 1.0f : 0.0f,
                                            c[3] >= 1.0f ? 1.0f : 0.0f);
                    *reinterpret_cast<float2*>(o + (size_t)row * Nout + col) = v0;
                    *reinterpret_cast<float2*>(o + (size_t)(row + 8) * Nout + col) = v1;
                }
            }
        }
    }
}

// ---------------- host launcher ----------------
extern "C" void kernel_launch(void* const* d_in, const int* in_sizes, int n_in,
                              void* d_out, int out_size)
{
    const float* x  = (const float*)d_in[0];  // [4096, 3136] binary
    const float* W1 = (const float*)d_in[1];  // [6272, 3136]
    const float* W2 = (const float*)d_in[2];  // [500, 6272]
    float* out = (float*)d_out;               // [4096, 500]

    __nv_bfloat16 *xb, *s1b, *w1l, *w2l;
    float* cb1; int* cnt;
    cudaGetSymbolAddress((void**)&xb,  g_xb);
    cudaGetSymbolAddress((void**)&s1b, g_s1b);
    cudaGetSymbolAddress((void**)&w1l, g_w1l);
    cudaGetSymbolAddress((void**)&w2l, g_w2l);
    cudaGetSymbolAddress((void**)&cb1, g_cb1);
    cudaGetSymbolAddress((void**)&cnt, g_cnt);

    cudaMemsetAsync(cnt, 0, sizeof(int));

    // converters
    {
        int n4 = (B_DIM * IN_DIM) / 4;
        conv_bf16_kernel<<<(n4 + 255) / 256, 256>>>(
            (const float4*)x, (__nv_bfloat162*)xb, n4);
    }
    {
        size_t n = (size_t)FEAT_DIM * IN_DIM;
        int n4 = (int)(n / 4);
        split2_kernel<<<(n4 + 255) / 256, 256>>>((const float4*)W1, w1l, n, n4);
        colbound_kernel<<<FEAT_DIM / 8, 256>>>(W1, cb1, IN_DIM);
    }
    {
        size_t n = (size_t)OUT_DIM * FEAT_DIM;
        int n4 = (int)(n / 4);
        split3_kernel<<<(n4 + 255) / 256, 256>>>((const float4*)W2, w2l, n, n4);
    }

    // GEMM1: s1 = step(x @ W1^T), 2-limb + certified fixup. [4096 x 6272]
    {
        constexpr int SMEM = STAGES * 3 * 128 * 64;   // 72 KB
        cudaFuncSetAttribute(spike_mma_gemm<2, true, true>,
                             cudaFuncAttributeMaxDynamicSharedMemorySize, SMEM);
        dim3 grid(B_DIM / 128, FEAT_DIM / 128);       // (32, 49) M-fast
        spike_mma_gemm<2, true, true><<<grid, 256, SMEM>>>(
            xb, w1l, (size_t)FEAT_DIM * IN_DIM, cb1, (void*)s1b, IN_DIM, FEAT_DIM);
    }
    // exact fp32 fixup of ambiguous hidden elements
    fixup1_kernel<<<256, 256>>>(x, W1, s1b);

    // GEMM2: out = step(s1 @ W2^T), 3-limb exact. [4096 x 500]
    {
        constexpr int SMEM = STAGES * 4 * 128 * 64;   // 96 KB
        cudaFuncSetAttribute(spike_mma_gemm<3, false, false>,
                             cudaFuncAttributeMaxDynamicSharedMemorySize, SMEM);
        dim3 grid(B_DIM / 128, (OUT_DIM + 127) / 128);  // (32, 4)
        spike_mma_gemm<3, false, false><<<grid, 256, SMEM>>>(
            s1b, w2l, (size_t)OUT_DIM * FEAT_DIM, nullptr, (void*)out, FEAT_DIM, OUT_DIM);
    }
}

// round 9
// speedup vs baseline: 1.3186x; 1.0074x over previous
#include <cuda_runtime.h>
#include <cuda_bf16.h>
#include <cstdint>
#include <cstddef>

#define B_DIM    4096
#define IN_DIM   3136
#define FEAT_DIM 6272
#define OUT_DIM  500
#define WL1_CAP  (1 << 20)
#define WL2_CAP  (1 << 16)

// ---------------- static device scratch (allocation-free) ----------------
__device__ __nv_bfloat16 g_xb [(size_t)B_DIM * IN_DIM];     // x as bf16 (exact)
__device__ __nv_bfloat16 g_s1b[(size_t)B_DIM * FEAT_DIM];   // hidden spikes bf16 (exact)
__device__ __nv_bfloat16 g_w1l[2ull * FEAT_DIM * IN_DIM];   // W1 limbs hi/mid
__device__ __nv_bfloat16 g_w2l[2ull * OUT_DIM * FEAT_DIM];  // W2 limbs hi/mid
__device__ float         g_cb1[FEAT_DIM];                   // per-col residual bound L1
__device__ float         g_cb2[512];                        // per-col residual bound L2
__device__ int           g_cnt[2];                          // worklist counters
__device__ unsigned      g_list1[WL1_CAP];                  // ambiguous v1 elements
__device__ unsigned      g_list2[WL2_CAP];                  // ambiguous v2 elements

// ---------------- PTX helpers ----------------
__device__ __forceinline__ uint32_t smem_u32(const void* p) {
    uint32_t a;
    asm("{ .reg .u64 t; cvta.to.shared.u64 t, %1; cvt.u32.u64 %0, t; }" : "=r"(a) : "l"(p));
    return a;
}
__device__ __forceinline__ void cp_async16(uint32_t dst, const void* src, int src_bytes) {
    asm volatile("cp.async.cg.shared.global [%0], [%1], 16, %2;"
                 :: "r"(dst), "l"(src), "r"(src_bytes) : "memory");
}
__device__ __forceinline__ void cp_commit() {
    asm volatile("cp.async.commit_group;" ::: "memory");
}
template <int N>
__device__ __forceinline__ void cp_wait() {
    asm volatile("cp.async.wait_group %0;" :: "n"(N) : "memory");
}
__device__ __forceinline__ void ldm_x4(uint32_t* r, uint32_t a) {
    asm volatile("ldmatrix.sync.aligned.m8n8.x4.shared.b16 {%0,%1,%2,%3}, [%4];"
                 : "=r"(r[0]), "=r"(r[1]), "=r"(r[2]), "=r"(r[3]) : "r"(a));
}
__device__ __forceinline__ void mma_bf16(float* c, const uint32_t* a, uint32_t b0, uint32_t b1) {
    asm volatile(
        "mma.sync.aligned.m16n8k16.row.col.f32.bf16.bf16.f32 "
        "{%0,%1,%2,%3}, {%4,%5,%6,%7}, {%8,%9}, {%0,%1,%2,%3};"
        : "+f"(c[0]), "+f"(c[1]), "+f"(c[2]), "+f"(c[3])
        : "r"(a[0]), "r"(a[1]), "r"(a[2]), "r"(a[3]), "r"(b0), "r"(b1));
}

// ---------------- converter kernels ----------------
__global__ void conv_bf16_kernel(const float4* __restrict__ in,
                                 __nv_bfloat162* __restrict__ out, int n4) {
    int i = blockIdx.x * blockDim.x + threadIdx.x;
    if (i < n4) {
        float4 v = in[i];
        out[i * 2 + 0] = __nv_bfloat162(__float2bfloat16_rn(v.x), __float2bfloat16_rn(v.y));
        out[i * 2 + 1] = __nv_bfloat162(__float2bfloat16_rn(v.z), __float2bfloat16_rn(v.w));
    }
}

// 2-limb split (hi+mid) fused with per-row residual-bound accumulation:
//   cb[row] += sum |w - hi - mid|   (row = output column of the GEMM)
__global__ void split2_cb_kernel(const float4* __restrict__ in,
                                 __nv_bfloat16* __restrict__ limbs,
                                 float* __restrict__ cb,
                                 size_t n, int n4, int K) {
    int i = blockIdx.x * blockDim.x + threadIdx.x;
    if (i >= n4) return;
    float4 v = in[i];
    float w[4] = {v.x, v.y, v.z, v.w};
    __nv_bfloat16 hi[4], mi[4];
    float rsum = 0.0f;
#pragma unroll
    for (int j = 0; j < 4; j++) {
        float f = w[j];
        hi[j] = __float2bfloat16_rn(f);
        float r1 = f - __bfloat162float(hi[j]);
        mi[j] = __float2bfloat16_rn(r1);
        rsum += fabsf(r1 - __bfloat162float(mi[j]));
    }
    __nv_bfloat162* o0 = reinterpret_cast<__nv_bfloat162*>(limbs);
    __nv_bfloat162* o1 = reinterpret_cast<__nv_bfloat162*>(limbs + n);
    o0[i * 2 + 0] = __nv_bfloat162(hi[0], hi[1]); o0[i * 2 + 1] = __nv_bfloat162(hi[2], hi[3]);
    o1[i * 2 + 0] = __nv_bfloat162(mi[0], mi[1]); o1[i * 2 + 1] = __nv_bfloat162(mi[2], mi[3]);

    // warp-aggregated bound accumulation (K%4==0 so all 4 elems share a row)
    const int row = (int)(((size_t)i * 4) / (size_t)K);
    const int first = __shfl_sync(0xFFFFFFFFu, row, 0);
    const int last  = __shfl_sync(0xFFFFFFFFu, row, 31);
    if (first == last) {
        float s = rsum;
#pragma unroll
        for (int o = 16; o; o >>= 1) s += __shfl_xor_sync(0xFFFFFFFFu, s, o);
        if ((threadIdx.x & 31) == 0) atomicAdd(&cb[row], s);
    } else {
        atomicAdd(&cb[row], rsum);
    }
}

// exact fp32 recompute of ambiguous v1 elements -> rewrite s1 spike
__global__ void fixup1_kernel(const float* __restrict__ x, const float* __restrict__ W1,
                              __nv_bfloat16* __restrict__ s1b) {
    const int warp = (blockIdx.x * blockDim.x + threadIdx.x) >> 5;
    const int lane = threadIdx.x & 31;
    const int nwarp = (gridDim.x * blockDim.x) >> 5;
    int cnt = g_cnt[0]; if (cnt > WL1_CAP) cnt = WL1_CAP;
    for (int w = warp; w < cnt; w += nwarp) {
        const unsigned idx = g_list1[w];
        const int b = idx / FEAT_DIM, j = idx % FEAT_DIM;
        const float* xr = x  + (size_t)b * IN_DIM;
        const float* wr = W1 + (size_t)j * IN_DIM;
        float s = 0.0f;
        for (int i = lane; i < IN_DIM; i += 32) s = fmaf(xr[i], wr[i], s);
#pragma unroll
        for (int o = 16; o; o >>= 1) s += __shfl_xor_sync(0xFFFFFFFFu, s, o);
        if (lane == 0)
            s1b[(size_t)b * FEAT_DIM + j] = __float2bfloat16(s >= 1.0f ? 1.0f : 0.0f);
    }
}

// exact fp32 recompute of ambiguous v2 elements -> rewrite output spike
__global__ void fixup2_kernel(const __nv_bfloat16* __restrict__ s1b,
                              const float* __restrict__ W2, float* __restrict__ out) {
    const int warp = (blockIdx.x * blockDim.x + threadIdx.x) >> 5;
    const int lane = threadIdx.x & 31;
    const int nwarp = (gridDim.x * blockDim.x) >> 5;
    int cnt = g_cnt[1]; if (cnt > WL2_CAP) cnt = WL2_CAP;
    for (int w = warp; w < cnt; w += nwarp) {
        const unsigned idx = g_list2[w];
        const int b = idx / OUT_DIM, j = idx % OUT_DIM;
        const __nv_bfloat16* sr = s1b + (size_t)b * FEAT_DIM;
        const float* wr = W2 + (size_t)j * FEAT_DIM;
        float s = 0.0f;
        for (int i = lane; i < FEAT_DIM; i += 32)
            s = fmaf(__bfloat162float(sr[i]), wr[i], s);
#pragma unroll
        for (int o = 16; o; o >>= 1) s += __shfl_xor_sync(0xFFFFFFFFu, s, o);
        if (lane == 0)
            out[(size_t)b * OUT_DIM + j] = (s >= 1.0f) ? 1.0f : 0.0f;
    }
}

// ---------------- fused mma.sync spike GEMM ----------------
//  C[M,Nout] = step( A[M,K] @ W[Nout,K]^T ), W as NL bf16 limbs (shared acc).
//  128x128 CTA tile, BK=32, 256 threads = 8 warps (4m x 2n), warp tile 32x64.
//  WL != 0: push |v-1| < colbound[col]+slack to worklist WL for exact fixup.
#define STAGES 4

template <int NL, bool OUT_BF16, int WL>
__global__ __launch_bounds__(256, 2)
void spike_mma_gemm(const __nv_bfloat16* __restrict__ A,
                    const __nv_bfloat16* __restrict__ Wl, size_t limbStride,
                    const float* __restrict__ colbound,
                    void* __restrict__ Cout, int K, int Nout)
{
    constexpr int STAGE_BYTES = (1 + NL) * 128 * 64;

    extern __shared__ char smem[];
    const int tid  = threadIdx.x;
    const int lane = tid & 31;
    const int wid  = tid >> 5;
    const int wm   = wid & 3;
    const int wn   = wid >> 2;
    const int rowBase = blockIdx.x * 128;   // M-fast grid: W slab reused in L2
    const int colBase = blockIdx.y * 128;

    const int rL  = lane & 15;
    const int ccL = lane >> 4;

    float acc[2][8][4];
#pragma unroll
    for (int i = 0; i < 2; i++)
#pragma unroll
        for (int j = 0; j < 8; j++)
#pragma unroll
            for (int k = 0; k < 4; k++) acc[i][j][k] = 0.0f;

    const uint32_t smem_base = smem_u32(smem);
    const int ITERS = K / 32;

    auto load_stage = [&](int it) {
        const int s  = it % STAGES;
        const int kt = it * 32;
        const uint32_t stA = smem_base + s * STAGE_BYTES;
        const uint32_t stB = stA + 128 * 64;
#pragma unroll
        for (int i = 0; i < 2; i++) {
            const int idx = tid * 2 + i;            // 0..511
            const int r = idx >> 2, c = idx & 3;
            const uint32_t d = stA + r * 64 + (((c ^ (r & 3)) << 4));
            cp_async16(d, A + (size_t)(rowBase + r) * K + kt + c * 8, 16);
        }
#pragma unroll
        for (int j = 0; j < 2 * NL; j++) {
            const int idx = tid + j * 256;          // 0..NL*512-1
            const int limb = idx >> 9, rem = idx & 511;
            const int r = rem >> 2, c = rem & 3;
            const int gn = colBase + r;
            const int ok = (gn < Nout);
            const int gns = ok ? gn : (Nout - 1);
            const uint32_t d = stB + limb * 8192 + r * 64 + (((c ^ (r & 3)) << 4));
            cp_async16(d, Wl + (size_t)limb * limbStride + (size_t)gns * K + kt + c * 8,
                       ok ? 16 : 0);
        }
        cp_commit();
    };

    load_stage(0);
    load_stage(1);
    load_stage(2);

    for (int it = 0; it < ITERS; ++it) {
        cp_wait<2>();
        __syncthreads();
        if (it + 3 < ITERS) load_stage(it + 3);

        const int s = it % STAGES;
        const uint32_t stA = smem_base + s * STAGE_BYTES;
        const uint32_t stB = stA + 128 * 64;

#pragma unroll
        for (int ks = 0; ks < 2; ks++) {
            uint32_t afr[2][4];
#pragma unroll
            for (int mt = 0; mt < 2; mt++) {
                const int row = wm * 32 + mt * 16 + rL;
                const uint32_t ad = stA + row * 64 + (((ccL + 2 * ks) ^ (row & 3)) << 4);
                ldm_x4(afr[mt], ad);
            }
#pragma unroll
            for (int limb = 0; limb < NL; limb++) {
                uint32_t bfr[4][4];
#pragma unroll
                for (int nb = 0; nb < 4; nb++) {
                    const int row = wn * 64 + nb * 16 + rL;
                    const uint32_t bd = stB + limb * 8192 + row * 64 +
                                        (((ccL + 2 * ks) ^ (row & 3)) << 4);
                    ldm_x4(bfr[nb], bd);
                }
#pragma unroll
                for (int mt = 0; mt < 2; mt++)
#pragma unroll
                    for (int nb = 0; nb < 4; nb++) {
                        mma_bf16(acc[mt][nb * 2 + 0], afr[mt], bfr[nb][0], bfr[nb][2]);
                        mma_bf16(acc[mt][nb * 2 + 1], afr[mt], bfr[nb][1], bfr[nb][3]);
                    }
            }
        }
    }

    // ---- epilogue: threshold + stores (+ ambiguity worklist when WL) ----
    const int g = lane >> 2;
    const int t = lane & 3;
#pragma unroll
    for (int mt = 0; mt < 2; mt++) {
#pragma unroll
        for (int nt = 0; nt < 8; nt++) {
            const float* c = acc[mt][nt];
            const int row = rowBase + wm * 32 + mt * 16 + g;
            const int col = colBase + wn * 64 + nt * 8 + 2 * t;
            if (WL != 0 && col < Nout) {
                const float b0 = colbound[col]     + 3e-5f;
                const float b1 = colbound[col + 1] + 3e-5f;
                const float m[4] = {fabsf(c[0] - 1.0f), fabsf(c[1] - 1.0f),
                                    fabsf(c[2] - 1.0f), fabsf(c[3] - 1.0f)};
                const unsigned base0 = (unsigned)row * (unsigned)Nout + col;
                const unsigned base1 = (unsigned)(row + 8) * (unsigned)Nout + col;
                int* cntp = &g_cnt[WL - 1];
                unsigned* listp = (WL == 1) ? g_list1 : g_list2;
                const int cap = (WL == 1) ? WL1_CAP : WL2_CAP;
                if (m[0] < b0) { int p = atomicAdd(cntp, 1); if (p < cap) listp[p] = base0; }
                if (m[1] < b1) { int p = atomicAdd(cntp, 1); if (p < cap) listp[p] = base0 + 1; }
                if (m[2] < b0) { int p = atomicAdd(cntp, 1); if (p < cap) listp[p] = base1; }
                if (m[3] < b1) { int p = atomicAdd(cntp, 1); if (p < cap) listp[p] = base1 + 1; }
            }
            if (OUT_BF16) {
                __nv_bfloat16* o = (__nv_bfloat16*)Cout;
                __nv_bfloat162 v0(__float2bfloat16(c[0] >= 1.0f ? 1.0f : 0.0f),
                                  __float2bfloat16(c[1] >= 1.0f ? 1.0f : 0.0f));
                __nv_bfloat162 v1(__float2bfloat16(c[2] >= 1.0f ? 1.0f : 0.0f),
                                  __float2bfloat16(c[3] >= 1.0f ? 1.0f : 0.0f));
                *reinterpret_cast<__nv_bfloat162*>(o + (size_t)row * Nout + col) = v0;
                *reinterpret_cast<__nv_bfloat162*>(o + (size_t)(row + 8) * Nout + col) = v1;
            } else {
                float* o = (float*)Cout;
                if (col < Nout) {
                    float2 v0 = make_float2(c[0] >= 1.0f ? 1.0f : 0.0f,
                                            c[1] >= 1.0f ? 1.0f : 0.0f);
                    float2 v1 = make_float2(c[2] >= 1.0f ? 1.0f : 0.0f,
                                            c[3] >= 1.0f ? 1.0f : 0.0f);
                    *reinterpret_cast<float2*>(o + (size_t)row * Nout + col) = v0;
                    *reinterpret_cast<float2*>(o + (size_t)(row + 8) * Nout + col) = v1;
                }
            }
        }
    }
}

// ---------------- host launcher ----------------
extern "C" void kernel_launch(void* const* d_in, const int* in_sizes, int n_in,
                              void* d_out, int out_size)
{
    const float* x  = (const float*)d_in[0];  // [4096, 3136] binary
    const float* W1 = (const float*)d_in[1];  // [6272, 3136]
    const float* W2 = (const float*)d_in[2];  // [500, 6272]
    float* out = (float*)d_out;               // [4096, 500]

    __nv_bfloat16 *xb, *s1b, *w1l, *w2l;
    float *cb1, *cb2; int* cnt;
    cudaGetSymbolAddress((void**)&xb,  g_xb);
    cudaGetSymbolAddress((void**)&s1b, g_s1b);
    cudaGetSymbolAddress((void**)&w1l, g_w1l);
    cudaGetSymbolAddress((void**)&w2l, g_w2l);
    cudaGetSymbolAddress((void**)&cb1, g_cb1);
    cudaGetSymbolAddress((void**)&cb2, g_cb2);
    cudaGetSymbolAddress((void**)&cnt, g_cnt);

    cudaMemsetAsync(cnt, 0, 2 * sizeof(int));
    cudaMemsetAsync(cb1, 0, FEAT_DIM * sizeof(float));
    cudaMemsetAsync(cb2, 0, 512 * sizeof(float));

    // converters (+ fused residual bounds)
    {
        int n4 = (B_DIM * IN_DIM) / 4;
        conv_bf16_kernel<<<(n4 + 255) / 256, 256>>>(
            (const float4*)x, (__nv_bfloat162*)xb, n4);
    }
    {
        size_t n = (size_t)FEAT_DIM * IN_DIM;
        int n4 = (int)(n / 4);
        split2_cb_kernel<<<(n4 + 255) / 256, 256>>>(
            (const float4*)W1, w1l, cb1, n, n4, IN_DIM);
    }
    {
        size_t n = (size_t)OUT_DIM * FEAT_DIM;
        int n4 = (int)(n / 4);
        split2_cb_kernel<<<(n4 + 255) / 256, 256>>>(
            (const float4*)W2, w2l, cb2, n, n4, FEAT_DIM);
    }

    // GEMM1: s1 = step(x @ W1^T), 2-limb + certified fixup. [4096 x 6272]
    {
        constexpr int SMEM = STAGES * 3 * 128 * 64;   // 96 KB
        cudaFuncSetAttribute(spike_mma_gemm<2, true, 1>,
                             cudaFuncAttributeMaxDynamicSharedMemorySize, SMEM);
        dim3 grid(B_DIM / 128, FEAT_DIM / 128);       // (32, 49) M-fast
        spike_mma_gemm<2, true, 1><<<grid, 256, SMEM>>>(
            xb, w1l, (size_t)FEAT_DIM * IN_DIM, cb1, (void*)s1b, IN_DIM, FEAT_DIM);
    }
    // exact fp32 fixup of ambiguous hidden elements
    fixup1_kernel<<<256, 256>>>(x, W1, s1b);

    // GEMM2: out = step(s1 @ W2^T), 2-limb + certified fixup. [4096 x 500]
    {
        constexpr int SMEM = STAGES * 3 * 128 * 64;   // 96 KB
        cudaFuncSetAttribute(spike_mma_gemm<2, false, 2>,
                             cudaFuncAttributeMaxDynamicSharedMemorySize, SMEM);
        dim3 grid(B_DIM / 128, (OUT_DIM + 127) / 128);  // (32, 4)
        spike_mma_gemm<2, false, 2><<<grid, 256, SMEM>>>(
            s1b, w2l, (size_t)OUT_DIM * FEAT_DIM, cb2, (void*)out, FEAT_DIM, OUT_DIM);
    }
    // exact fp32 fixup of ambiguous output elements
    fixup2_kernel<<<64, 256>>>(s1b, W2, out);
}